// round 10
// baseline (speedup 1.0000x reference)
#include <cuda_runtime.h>
#include <cuda_fp16.h>
#include <cstdint>
#include <cstddef>

// ---------------------------------------------------------------------------
// Problem constants
// ---------------------------------------------------------------------------
#define HIDN   512
#define BATCH  64
#define SEQT   256
#define MTOT   (BATCH * SEQT)       // 16384
#define G4     (4 * HIDN)           // 2048
#define NCLS   50257
#define SEQH   (BATCH * HIDN)       // 32768

// ---------------------------------------------------------------------------
// Static device scratch
// ---------------------------------------------------------------------------
__device__ float  d_xg[(size_t)MTOT * G4];               // layer-0 gate preacts
__device__ __half d_h0seq[(size_t)(SEQT + 1) * SEQH];    // slot 0 = zeros
__device__ __half d_h1seq[(size_t)(SEQT + 1) * SEQH];
__device__ float  d_hlast[SEQH];                         // h1[256] fp32
// per-block progress flags, one 128B line each (no atomic contention)
__device__ unsigned d_flag0[64 * 32];
__device__ unsigned d_flag1[64 * 32];

__global__ void zero_h(__half* a, __half* b, int n)
{
    for (int i = blockIdx.x * blockDim.x + threadIdx.x; i < n;
         i += gridDim.x * blockDim.x) {
        a[i] = __float2half(0.0f);
        b[i] = __float2half(0.0f);
    }
}

__global__ void zero_flags()
{
    int i = blockIdx.x * blockDim.x + threadIdx.x;
    if (i < 64 * 32) { d_flag0[i] = 0; d_flag1[i] = 0; }
}

// ---------------------------------------------------------------------------
// Common helpers
// ---------------------------------------------------------------------------
__device__ __forceinline__ unsigned f2tf(float f)
{
    unsigned u;
    asm("cvt.rna.tf32.f32 %0, %1;" : "=r"(u) : "f"(f));
    return u;
}

__device__ __forceinline__ void mma_tf32(float* c, unsigned a0, unsigned a1,
                                         unsigned a2, unsigned a3,
                                         unsigned b0, unsigned b1)
{
    asm volatile(
        "mma.sync.aligned.m16n8k8.row.col.f32.tf32.tf32.f32 "
        "{%0,%1,%2,%3}, {%4,%5,%6,%7}, {%8,%9}, {%0,%1,%2,%3};\n"
        : "+f"(c[0]), "+f"(c[1]), "+f"(c[2]), "+f"(c[3])
        : "r"(a0), "r"(a1), "r"(a2), "r"(a3), "r"(b0), "r"(b1));
}

#define LDSM4(r0, r1, r2, r3, addr)                                        \
    asm volatile("ldmatrix.sync.aligned.m8n8.x4.shared.b16 "               \
                 "{%0,%1,%2,%3}, [%4];"                                    \
                 : "=r"(r0), "=r"(r1), "=r"(r2), "=r"(r3) : "r"(addr))

#define MMA16816(c, a0, a1, a2, a3, b0, b1)                                \
    asm volatile("mma.sync.aligned.m16n8k16.row.col.f32.f16.f16.f32 "      \
                 "{%0,%1,%2,%3}, {%4,%5,%6,%7}, {%8,%9}, {%0,%1,%2,%3};"   \
                 : "+f"((c)[0]), "+f"((c)[1]), "+f"((c)[2]), "+f"((c)[3])  \
                 : "r"(a0), "r"(a1), "r"(a2), "r"(a3), "r"(b0), "r"(b1))

__device__ __forceinline__ float sigm_f(float x)
{
    return __fdividef(1.0f, 1.0f + __expf(-x));
}

__device__ __forceinline__ float tanh_f(float x)
{
    float e = __expf(2.0f * fabsf(x));
    float r = 1.0f - __fdividef(2.0f, e + 1.0f);
    return copysignf(r, x);
}

// ---------------------------------------------------------------------------
// Flag-vector barrier protocol (contention-free):
//   producer block b publishes tick v:  st.release.gpu flags[b*32] = v
//   consumer warp polls all 64 flags (2 per lane) until min >= target
// ---------------------------------------------------------------------------
__device__ __forceinline__ void flag_set(unsigned* f, unsigned v)
{
    asm volatile("st.release.gpu.global.u32 [%0], %1;"
                 :: "l"(f), "r"(v) : "memory");
}

__device__ __forceinline__ void flags_wait(const unsigned* flags,
                                           unsigned target, int lane)
{
    const unsigned* p0 = flags + lane * 32;
    const unsigned* p1 = flags + (lane + 32) * 32;
    unsigned v0, v1;
    do {
        asm volatile("ld.acquire.gpu.global.u32 %0, [%1];"
                     : "=r"(v0) : "l"(p0) : "memory");
        asm volatile("ld.acquire.gpu.global.u32 %0, [%1];"
                     : "=r"(v1) : "l"(p1) : "memory");
    } while (!__all_sync(0xFFFFFFFFu, (v0 >= target) && (v1 >= target)));
}

// ---------------------------------------------------------------------------
// tf32 mma GEMM, 128x128 tile, 512 threads (16 warps, 4x4), warp tile 32x32.
//   C[m][n] = sum_k A'[m][k]*B[n][k] + bias1[n] (+ bias2[n])
//   Optional embedding row gather on A. Full M/N guards. K multiple of 16.
// ---------------------------------------------------------------------------
__global__ __launch_bounds__(512)
void gemm_mma2(const float* __restrict__ A, const float* __restrict__ B,
               float* __restrict__ C,
               const float* __restrict__ bias1, const float* __restrict__ bias2,
               const int* __restrict__ gX,
               int M, int N, int K)
{
    __shared__ unsigned As[128 * 20];
    __shared__ unsigned Bs[128 * 20];

    const int tid  = threadIdx.x;
    const int lane = tid & 31;
    const int warp = tid >> 5;
    const int wm   = warp >> 2;
    const int wn   = warp & 3;
    const int gid  = lane >> 2;
    const int tig  = lane & 3;
    const int m0   = blockIdx.y * 128;
    const int n0   = blockIdx.x * 128;

    const int lrow = tid >> 2;
    const int lkq  = (tid & 3) * 4;

    const float* Ap;
    {
        int am = m0 + lrow;
        long long r;
        if (gX)          r = gX[(am & 63) * SEQT + (am >> 6)];
        else if (am < M) r = am;
        else             r = 0;
        Ap = A + (size_t)r * K + lkq;
    }
    const float* Bp;
    {
        int bn = n0 + lrow;
        Bp = B + (size_t)(bn < N ? bn : 0) * K + lkq;
    }

    float acc[2][4][4];
#pragma unroll
    for (int a = 0; a < 2; a++)
#pragma unroll
        for (int b = 0; b < 4; b++)
#pragma unroll
            for (int c = 0; c < 4; c++) acc[a][b][c] = 0.0f;

    for (int k0 = 0; k0 < K; k0 += 16) {
        float4 av = *reinterpret_cast<const float4*>(Ap + k0);
        float4 bv = *reinterpret_cast<const float4*>(Bp + k0);

        __syncthreads();
        {
            uint4 ta = make_uint4(f2tf(av.x), f2tf(av.y), f2tf(av.z), f2tf(av.w));
            uint4 tb = make_uint4(f2tf(bv.x), f2tf(bv.y), f2tf(bv.z), f2tf(bv.w));
            *reinterpret_cast<uint4*>(&As[lrow * 20 + lkq]) = ta;
            *reinterpret_cast<uint4*>(&Bs[lrow * 20 + lkq]) = tb;
        }
        __syncthreads();

#pragma unroll
        for (int kk = 0; kk < 16; kk += 8) {
            unsigned afr[2][4];
#pragma unroll
            for (int mi = 0; mi < 2; mi++) {
                int base = (wm * 32 + mi * 16 + gid) * 20 + kk + tig;
                afr[mi][0] = As[base];
                afr[mi][1] = As[base + 8 * 20];
                afr[mi][2] = As[base + 4];
                afr[mi][3] = As[base + 8 * 20 + 4];
            }
#pragma unroll
            for (int ni = 0; ni < 4; ni++) {
                int nb = (wn * 32 + ni * 8 + gid) * 20 + kk + tig;
                unsigned b0 = Bs[nb];
                unsigned b1 = Bs[nb + 4];
                mma_tf32(acc[0][ni], afr[0][0], afr[0][1], afr[0][2], afr[0][3], b0, b1);
                mma_tf32(acc[1][ni], afr[1][0], afr[1][1], afr[1][2], afr[1][3], b0, b1);
            }
        }
    }

#pragma unroll
    for (int ni = 0; ni < 4; ni++) {
        int col = n0 + wn * 32 + ni * 8 + 2 * tig;
        float bs0 = 0.f, bs1 = 0.f;
        if (col < N)     bs0 = bias1[col]     + (bias2 ? bias2[col]     : 0.0f);
        if (col + 1 < N) bs1 = bias1[col + 1] + (bias2 ? bias2[col + 1] : 0.0f);
#pragma unroll
        for (int mi = 0; mi < 2; mi++) {
            int row = m0 + wm * 32 + mi * 16 + gid;
#pragma unroll
            for (int rr = 0; rr < 2; rr++) {
                int r = row + rr * 8;
                if (r < M) {
                    if (col < N)
                        C[(size_t)r * N + col]     = acc[mi][ni][rr * 2]     + bs0;
                    if (col + 1 < N)
                        C[(size_t)r * N + col + 1] = acc[mi][ni][rr * 2 + 1] + bs1;
                }
            }
        }
    }
}

// ---------------------------------------------------------------------------
// Pipelined persistent LSTM, phase-split L1, flag-vector sync (R7 + new sync).
//   Blocks 0-63:  layer-0. g = h0_{t-1} @ w_hh0^T + xg0[t]   (k=512)
//   Blocks 64-127: layer-1. g = h1_{t-1} @ w_hh1^T (phase A, overlaps L0)
//                  + h0_t @ w_ih1^T (phase B) + (b_ih1 + b_hh1)
// Block owns 8 hidden units (32 gate cols). fp16 mma m16n8k16, fp32 acc.
// ---------------------------------------------------------------------------
#define GH   (32 * 65)
#define SHH  520                       // h buffer stride (halfs)

// stage one 512-wide fp16 h slice [64][512] -> h_s (stride SHH)
__device__ __forceinline__ void stage_h(__half* h_s, const __half* src, int tid)
{
    const uint4* s = (const uint4*)src;
#pragma unroll
    for (int i = 0; i < 8; i++) {
        int idx = tid + i * 512;
        int b = idx >> 6, kc = idx & 63;
        uint4 v = s[b * 64 + kc];
        *reinterpret_cast<uint4*>(h_s + b * SHH + kc * 8) = v;
    }
}

template<int SW>
__device__ __forceinline__ void mma_phase(float* acc0, float* acc1,
                                          unsigned hbase, unsigned wphase)
{
#pragma unroll
    for (int kk = 0; kk < 16; kk++) {
        unsigned ra0, ra1, ra2, ra3, rb0, rb1, rb2, rb3;
        LDSM4(ra0, ra1, ra2, ra3, hbase + kk * 32);
        LDSM4(rb0, rb1, rb2, rb3, wphase + kk * 32);
        MMA16816(acc0, ra0, ra1, ra2, ra3, rb0, rb2);
        MMA16816(acc1, ra0, ra1, ra2, ra3, rb1, rb3);
    }
}

template<bool IS_L1>
__device__ __forceinline__ void lstm_role(
    const float* __restrict__ xg,      // L0 only
    const float* __restrict__ wA,      // L0: w_hh0 ; L1: w_ih1
    const float* __restrict__ wB,      // L1: w_hh1
    const float* __restrict__ bi,      // L1: b_ih1
    const float* __restrict__ bh,      // L1: b_hh1
    int blk, char* smbase)
{
    constexpr int WKT = IS_L1 ? 1024 : 512;   // weight k extent
    constexpr int SW  = WKT + 8;              // w row stride (halfs)

    __half* h_s = (__half*)smbase;                    // 64 x SHH
    __half* w_s = h_s + 64 * SHH;                     // 32 x SW
    float*  c_s = (float*)(w_s + 32 * SW);            // 8 x 68
    float*  g_s = c_s + 8 * 68;                       // 2 x 32 x 65

    const int tid  = threadIdx.x;
    const int lane = tid & 31;
    const int warp = tid >> 5;
    const int ks   = warp >> 3;        // k half within a 512 slice
    const int wm   = (warp & 7) >> 1;
    const int wn   = warp & 1;

    // ---- preload W as fp16 (resident) -------------------------------------
#pragma unroll
    for (int i = 0; i < WKT / 64; i++) {
        int idx = tid + i * 512;               // 0 .. 32*WKT/4-1
        int r   = idx / (WKT / 4);             // 0..31
        int kq  = (idx % (WKT / 4)) * 4;
        int grow = (r >> 3) * 512 + blk * 8 + (r & 7);
        const float* src;
        if (IS_L1) src = (kq < 512) ? wA + (size_t)grow * 512 + kq
                                    : wB + (size_t)grow * 512 + (kq - 512);
        else       src = wA + (size_t)grow * 512 + kq;
        float4 v = *reinterpret_cast<const float4*>(src);
        __half2* dst = reinterpret_cast<__half2*>(w_s + r * SW + kq);
        dst[0] = __floats2half2_rn(v.x, v.y);
        dst[1] = __floats2half2_rn(v.z, v.w);
    }
    for (int i = tid; i < 8 * 68; i += 512) c_s[i] = 0.0f;

    // epilogue mapping: one (batch, unit) pair per thread
    const int eb   = tid >> 3;
    const int eul  = tid & 7;
    const int ucol = blk * 8 + eul;
    float bia[4] = {0.f, 0.f, 0.f, 0.f};
    if (IS_L1) {
#pragma unroll
        for (int q = 0; q < 4; q++)
            bia[q] = bi[q * 512 + ucol] + bh[q * 512 + ucol];
    }

    // ldmatrix base addresses
    unsigned hbase = (unsigned)__cvta_generic_to_shared(h_s)
                   + (unsigned)(((wm * 16 + (lane & 15)) * SHH
                                 + ks * 256 + ((lane >> 4) << 3)) * 2);
    unsigned wbase = (unsigned)__cvta_generic_to_shared(w_s)
                   + (unsigned)(((wn * 16 + (lane & 15)) * SW
                                 + ks * 256 + ((lane >> 4) << 3)) * 2);

    __syncthreads();

    for (int t = 0; t < SEQT; t++) {
        float acc0[4] = {0.f, 0.f, 0.f, 0.f};
        float acc1[4] = {0.f, 0.f, 0.f, 0.f};
        float px0 = 0.f, px1 = 0.f, px2 = 0.f, px3 = 0.f;

        if (IS_L1) {
            // ---- self wait (h1[t] ready) + phase A on own data ------------
            if (warp == 0) flags_wait(d_flag1, (unsigned)t, lane);
            __syncthreads();
            stage_h(h_s, d_h1seq + (size_t)t * SEQH, tid);
            __syncthreads();
            // phase A: w cols 512..1023 (w_hh1) — overlaps L0's step t
            mma_phase<SW>(acc0, acc1, hbase, wbase + 512 * 2);

            // ---- dependency wait on layer-0 step t -------------------------
            if (warp == 0) flags_wait(d_flag0, (unsigned)(t + 1), lane);
            __syncthreads();   // also guarantees phase-A LDSMs done
            stage_h(h_s, d_h0seq + (size_t)(t + 1) * SEQH, tid);
            __syncthreads();
            // phase B: w cols 0..511 (w_ih1)
            mma_phase<SW>(acc0, acc1, hbase, wbase);
        } else {
            // xg prefetch (independent of barrier)
            const float* xp = xg + (size_t)t * (BATCH * G4) + (size_t)eb * G4;
            px0 = xp[ucol];
            px1 = xp[512  + ucol];
            px2 = xp[1024 + ucol];
            px3 = xp[1536 + ucol];

            if (warp == 0) flags_wait(d_flag0, (unsigned)t, lane);
            __syncthreads();
            stage_h(h_s, d_h0seq + (size_t)t * SEQH, tid);
            __syncthreads();
            mma_phase<SW>(acc0, acc1, hbase, wbase);
        }

        // ---- stage C frags: g_s[ks][col 0..31][batch 0..63] ----------------
        {
            float* gh = g_s + ks * GH;
            int b  = wm * 16 + (lane >> 2);
            int c0 = wn * 16 + (lane & 3) * 2;
            int c1 = c0 + 8;
            gh[(c0    ) * 65 + b    ] = acc0[0];
            gh[(c0 + 1) * 65 + b    ] = acc0[1];
            gh[(c0    ) * 65 + b + 8] = acc0[2];
            gh[(c0 + 1) * 65 + b + 8] = acc0[3];
            gh[(c1    ) * 65 + b    ] = acc1[0];
            gh[(c1 + 1) * 65 + b    ] = acc1[1];
            gh[(c1    ) * 65 + b + 8] = acc1[2];
            gh[(c1 + 1) * 65 + b + 8] = acc1[3];
        }
        __syncthreads();

        // ---- gates + cell update -------------------------------------------
        {
            float gi = g_s[( 0 + eul) * 65 + eb] + g_s[GH + ( 0 + eul) * 65 + eb];
            float gf = g_s[( 8 + eul) * 65 + eb] + g_s[GH + ( 8 + eul) * 65 + eb];
            float gg = g_s[(16 + eul) * 65 + eb] + g_s[GH + (16 + eul) * 65 + eb];
            float go = g_s[(24 + eul) * 65 + eb] + g_s[GH + (24 + eul) * 65 + eb];
            if (IS_L1) {
                gi += bia[0]; gf += bia[1]; gg += bia[2]; go += bia[3];
            } else {
                gi += px0; gf += px1; gg += px2; go += px3;
            }

            float i_t = sigm_f(gi);
            float f_t = sigm_f(gf);
            float g_t = tanh_f(gg);
            float o_t = sigm_f(go);

            float cn = f_t * c_s[eul * 68 + eb] + i_t * g_t;
            c_s[eul * 68 + eb] = cn;
            float hv = o_t * tanh_f(cn);
            __half* own = IS_L1 ? d_h1seq : d_h0seq;
            own[(size_t)(t + 1) * SEQH + eb * 512 + ucol] = __float2half(hv);
            if (IS_L1 && t == SEQT - 1)
                d_hlast[eb * 512 + ucol] = hv;
        }
        __syncthreads();
        if (tid == 0) {
            if (IS_L1) flag_set(&d_flag1[blk * 32], (unsigned)(t + 1));
            else       flag_set(&d_flag0[blk * 32], (unsigned)(t + 1));
        }
    }
}

__global__ __launch_bounds__(512)
void lstm_pipeline(const float* __restrict__ xg0,
                   const float* __restrict__ w_hh0,
                   const float* __restrict__ w_ih1,
                   const float* __restrict__ w_hh1,
                   const float* __restrict__ b_ih1,
                   const float* __restrict__ b_hh1)
{
    extern __shared__ char smbase[];
    if (blockIdx.x < 64) {
        lstm_role<false>(xg0, w_hh0, nullptr, nullptr, nullptr,
                         blockIdx.x, smbase);
    } else {
        lstm_role<true>(nullptr, w_ih1, w_hh1, b_ih1, b_hh1,
                        blockIdx.x - 64, smbase);
    }
}

// L1 smem: 64*520*2 + 32*1032*2 + 8*68*4 + 2*32*65*4 = 151424 B
#define PIPE_SMEM (64 * SHH * 2 + 32 * 1032 * 2 + 8 * 68 * 4 + 2 * 32 * 65 * 4)

// ---------------------------------------------------------------------------
// kernel_launch
// ---------------------------------------------------------------------------
extern "C" void kernel_launch(void* const* d_in, const int* in_sizes, int n_in,
                              void* d_out, int out_size)
{
    const int*   X     = (const int*)  d_in[0];
    const float* emb   = (const float*)d_in[1];
    const float* w_ih0 = (const float*)d_in[2];
    const float* w_hh0 = (const float*)d_in[3];
    const float* b_ih0 = (const float*)d_in[4];
    const float* b_hh0 = (const float*)d_in[5];
    const float* w_ih1 = (const float*)d_in[6];
    const float* w_hh1 = (const float*)d_in[7];
    const float* b_ih1 = (const float*)d_in[8];
    const float* b_hh1 = (const float*)d_in[9];
    const float* Wout  = (const float*)d_in[10];
    const float* bout  = (const float*)d_in[11];
    float* out = (float*)d_out;

    float *xg, *hlast;
    __half *h0s, *h1s;
    cudaGetSymbolAddress((void**)&xg,    d_xg);
    cudaGetSymbolAddress((void**)&h0s,   d_h0seq);
    cudaGetSymbolAddress((void**)&h1s,   d_h1seq);
    cudaGetSymbolAddress((void**)&hlast, d_hlast);

    cudaFuncSetAttribute(lstm_pipeline,
                         cudaFuncAttributeMaxDynamicSharedMemorySize,
                         PIPE_SMEM);

    // 1) zero h_0 slots + flags
    zero_h<<<32, 256>>>(h0s, h1s, SEQH);
    zero_flags<<<8, 256>>>();

    // 2) xg for layer 0 (embedding gather fused, tf32 mma)
    {
        dim3 grid(G4 / 128, MTOT / 128);
        gemm_mma2<<<grid, 512>>>(emb, w_ih0, xg, b_ih0, b_hh0, X,
                                 MTOT, G4, HIDN);
    }

    // 3) pipelined 2-layer recurrence (phase-split L1, flag-vector sync)
    lstm_pipeline<<<128, 512, PIPE_SMEM>>>(xg, w_hh0, w_ih1, w_hh1,
                                           b_ih1, b_hh1);

    // 4) logits = h1_last @ W^T + b  (guarded tf32 mma)
    {
        dim3 grid((NCLS + 127) / 128, 1);
        gemm_mma2<<<grid, 512>>>(hlast, Wout, out, bout, nullptr, nullptr,
                                 BATCH, NCLS, HIDN);
    }
}

// round 13
// speedup vs baseline: 1.1443x; 1.1443x over previous
#include <cuda_runtime.h>
#include <cuda_fp16.h>
#include <cstdint>
#include <cstddef>

// ---------------------------------------------------------------------------
// Problem constants
// ---------------------------------------------------------------------------
#define HIDN   512
#define BATCH  64
#define SEQT   256
#define MTOT   (BATCH * SEQT)       // 16384
#define G4     (4 * HIDN)           // 2048
#define NCLS   50257
#define SEQH   (BATCH * HIDN)       // 32768

// ---------------------------------------------------------------------------
// Static device scratch
// ---------------------------------------------------------------------------
__device__ float  d_xg[(size_t)MTOT * G4];               // layer-0 gate preacts
__device__ __half d_h0seq[(size_t)(SEQT + 1) * SEQH];    // slot 0 = zeros
__device__ __half d_h1seq[(size_t)(SEQT + 1) * SEQH];
__device__ float  d_hlast[SEQH];                         // h1[255] fp32
__device__ unsigned d_bars[64];                          // [0]=bar0, [32]=bar1

__global__ void zero_h(__half* a, __half* b, int n)
{
    for (int i = blockIdx.x * blockDim.x + threadIdx.x; i < n;
         i += gridDim.x * blockDim.x) {
        a[i] = __float2half(0.0f);
        b[i] = __float2half(0.0f);
    }
}

__global__ void zero_bar()
{
    if (threadIdx.x == 0) { d_bars[0] = 0; d_bars[32] = 0; }
}

// ---------------------------------------------------------------------------
// Common helpers
// ---------------------------------------------------------------------------
__device__ __forceinline__ unsigned f2tf(float f)
{
    unsigned u;
    asm("cvt.rna.tf32.f32 %0, %1;" : "=r"(u) : "f"(f));
    return u;
}

__device__ __forceinline__ void mma_tf32(float* c, unsigned a0, unsigned a1,
                                         unsigned a2, unsigned a3,
                                         unsigned b0, unsigned b1)
{
    asm volatile(
        "mma.sync.aligned.m16n8k8.row.col.f32.tf32.tf32.f32 "
        "{%0,%1,%2,%3}, {%4,%5,%6,%7}, {%8,%9}, {%0,%1,%2,%3};\n"
        : "+f"(c[0]), "+f"(c[1]), "+f"(c[2]), "+f"(c[3])
        : "r"(a0), "r"(a1), "r"(a2), "r"(a3), "r"(b0), "r"(b1));
}

#define LDSM4(r0, r1, r2, r3, addr)                                        \
    asm volatile("ldmatrix.sync.aligned.m8n8.x4.shared.b16 "               \
                 "{%0,%1,%2,%3}, [%4];"                                    \
                 : "=r"(r0), "=r"(r1), "=r"(r2), "=r"(r3) : "r"(addr))

// fp16-accumulator HMMA: 2x rate vs f32-acc on the legacy tensor path.
// D/C are 2 regs = 4 halfs: reg0 = (row r, col c),(r, c+1); reg1 = rows r+8.
#define MMA16816H(c, a0, a1, a2, a3, b0, b1)                               \
    asm volatile("mma.sync.aligned.m16n8k16.row.col.f16.f16.f16.f16 "      \
                 "{%0,%1}, {%2,%3,%4,%5}, {%6,%7}, {%0,%1};"               \
                 : "+r"((c)[0]), "+r"((c)[1])                              \
                 : "r"(a0), "r"(a1), "r"(a2), "r"(a3), "r"(b0), "r"(b1))

__device__ __forceinline__ float sigm_f(float x)
{
    return __fdividef(1.0f, 1.0f + __expf(-x));
}

__device__ __forceinline__ float tanh_f(float x)
{
    float e = __expf(2.0f * fabsf(x));
    float r = 1.0f - __fdividef(2.0f, e + 1.0f);
    return copysignf(r, x);
}

// ---------------------------------------------------------------------------
// tf32 mma GEMM, 128x128 tile, 512 threads (16 warps, 4x4), warp tile 32x32.
//   C[m][n] = sum_k A'[m][k]*B[n][k] + bias1[n] (+ bias2[n])
//   Optional embedding row gather on A. Full M/N guards. K multiple of 16.
// ---------------------------------------------------------------------------
__global__ __launch_bounds__(512)
void gemm_mma2(const float* __restrict__ A, const float* __restrict__ B,
               float* __restrict__ C,
               const float* __restrict__ bias1, const float* __restrict__ bias2,
               const int* __restrict__ gX,
               int M, int N, int K)
{
    __shared__ unsigned As[128 * 20];
    __shared__ unsigned Bs[128 * 20];

    const int tid  = threadIdx.x;
    const int lane = tid & 31;
    const int warp = tid >> 5;
    const int wm   = warp >> 2;
    const int wn   = warp & 3;
    const int gid  = lane >> 2;
    const int tig  = lane & 3;
    const int m0   = blockIdx.y * 128;
    const int n0   = blockIdx.x * 128;

    const int lrow = tid >> 2;
    const int lkq  = (tid & 3) * 4;

    const float* Ap;
    {
        int am = m0 + lrow;
        long long r;
        if (gX)          r = gX[(am & 63) * SEQT + (am >> 6)];
        else if (am < M) r = am;
        else             r = 0;
        Ap = A + (size_t)r * K + lkq;
    }
    const float* Bp;
    {
        int bn = n0 + lrow;
        Bp = B + (size_t)(bn < N ? bn : 0) * K + lkq;
    }

    float acc[2][4][4];
#pragma unroll
    for (int a = 0; a < 2; a++)
#pragma unroll
        for (int b = 0; b < 4; b++)
#pragma unroll
            for (int c = 0; c < 4; c++) acc[a][b][c] = 0.0f;

    for (int k0 = 0; k0 < K; k0 += 16) {
        float4 av = *reinterpret_cast<const float4*>(Ap + k0);
        float4 bv = *reinterpret_cast<const float4*>(Bp + k0);

        __syncthreads();
        {
            uint4 ta = make_uint4(f2tf(av.x), f2tf(av.y), f2tf(av.z), f2tf(av.w));
            uint4 tb = make_uint4(f2tf(bv.x), f2tf(bv.y), f2tf(bv.z), f2tf(bv.w));
            *reinterpret_cast<uint4*>(&As[lrow * 20 + lkq]) = ta;
            *reinterpret_cast<uint4*>(&Bs[lrow * 20 + lkq]) = tb;
        }
        __syncthreads();

#pragma unroll
        for (int kk = 0; kk < 16; kk += 8) {
            unsigned afr[2][4];
#pragma unroll
            for (int mi = 0; mi < 2; mi++) {
                int base = (wm * 32 + mi * 16 + gid) * 20 + kk + tig;
                afr[mi][0] = As[base];
                afr[mi][1] = As[base + 8 * 20];
                afr[mi][2] = As[base + 4];
                afr[mi][3] = As[base + 8 * 20 + 4];
            }
#pragma unroll
            for (int ni = 0; ni < 4; ni++) {
                int nb = (wn * 32 + ni * 8 + gid) * 20 + kk + tig;
                unsigned b0 = Bs[nb];
                unsigned b1 = Bs[nb + 4];
                mma_tf32(acc[0][ni], afr[0][0], afr[0][1], afr[0][2], afr[0][3], b0, b1);
                mma_tf32(acc[1][ni], afr[1][0], afr[1][1], afr[1][2], afr[1][3], b0, b1);
            }
        }
    }

#pragma unroll
    for (int ni = 0; ni < 4; ni++) {
        int col = n0 + wn * 32 + ni * 8 + 2 * tig;
        float bs0 = 0.f, bs1 = 0.f;
        if (col < N)     bs0 = bias1[col]     + (bias2 ? bias2[col]     : 0.0f);
        if (col + 1 < N) bs1 = bias1[col + 1] + (bias2 ? bias2[col + 1] : 0.0f);
#pragma unroll
        for (int mi = 0; mi < 2; mi++) {
            int row = m0 + wm * 32 + mi * 16 + gid;
#pragma unroll
            for (int rr = 0; rr < 2; rr++) {
                int r = row + rr * 8;
                if (r < M) {
                    if (col < N)
                        C[(size_t)r * N + col]     = acc[mi][ni][rr * 2]     + bs0;
                    if (col + 1 < N)
                        C[(size_t)r * N + col + 1] = acc[mi][ni][rr * 2 + 1] + bs1;
                }
            }
        }
    }
}

// ---------------------------------------------------------------------------
// Pipelined persistent LSTM, phase-split L1, f16-accumulator HMMA.
//   Blocks 0-63:  layer-0. g = h0_{t-1} @ w_hh0^T + xg0[t]   (k=512)
//   Blocks 64-127: layer-1. g = h1_{t-1} @ w_hh1^T (phase A, overlaps L0)
//                  + h0_t @ w_ih1^T (phase B) + (b_ih1 + b_hh1)
// Block owns 8 hidden units (32 gate cols). Each f16 accumulator chain is
// capped at 16 HMMA; phases and k-halves are reduced in fp32.
// ---------------------------------------------------------------------------
#define GH   (32 * 65)
#define SHH  520                       // h buffer stride (halfs)

// stage one 512-wide fp16 h slice [64][512] -> h_s (stride SHH)
__device__ __forceinline__ void stage_h(__half* h_s, const __half* src, int tid)
{
    const uint4* s = (const uint4*)src;
#pragma unroll
    for (int i = 0; i < 8; i++) {
        int idx = tid + i * 512;
        int b = idx >> 6, kc = idx & 63;
        uint4 v = s[b * 64 + kc];
        *reinterpret_cast<uint4*>(h_s + b * SHH + kc * 8) = v;
    }
}

// one 256-k phase with f16 accumulation (16 chained HMMA per accumulator)
__device__ __forceinline__ void mma_phase_h(unsigned* c0, unsigned* c1,
                                            unsigned hbase, unsigned wphase)
{
#pragma unroll
    for (int kk = 0; kk < 16; kk++) {
        unsigned ra0, ra1, ra2, ra3, rb0, rb1, rb2, rb3;
        LDSM4(ra0, ra1, ra2, ra3, hbase + kk * 32);
        LDSM4(rb0, rb1, rb2, rb3, wphase + kk * 32);
        MMA16816H(c0, ra0, ra1, ra2, ra3, rb0, rb2);
        MMA16816H(c1, ra0, ra1, ra2, ra3, rb1, rb3);
    }
}

// unpack f16x4 accumulator and add into fp32 accumulator
__device__ __forceinline__ void acc_add(float* f, const unsigned* c)
{
    __half2 h0 = *reinterpret_cast<const __half2*>(&c[0]);
    __half2 h1 = *reinterpret_cast<const __half2*>(&c[1]);
    float2 f0 = __half22float2(h0);
    float2 f1 = __half22float2(h1);
    f[0] += f0.x; f[1] += f0.y; f[2] += f1.x; f[3] += f1.y;
}

__device__ __forceinline__ void bar_red(unsigned* bar)
{
    asm volatile("red.release.gpu.global.add.u32 [%0], %1;"
                 :: "l"(bar), "r"(1u) : "memory");
}

__device__ __forceinline__ void bar_wait(unsigned* bar, unsigned target)
{
    unsigned v;
    do {
        asm volatile("ld.acquire.gpu.global.u32 %0, [%1];"
                     : "=r"(v) : "l"(bar) : "memory");
    } while (v < target);
}

template<bool IS_L1>
__device__ __forceinline__ void lstm_role(
    const float* __restrict__ xg,      // L0 only
    const float* __restrict__ wA,      // L0: w_hh0 ; L1: w_ih1
    const float* __restrict__ wB,      // L1: w_hh1
    const float* __restrict__ bi,      // L1: b_ih1
    const float* __restrict__ bh,      // L1: b_hh1
    int blk, char* smbase)
{
    constexpr int WKT = IS_L1 ? 1024 : 512;   // weight k extent
    constexpr int SW  = WKT + 8;              // w row stride (halfs)

    __half* h_s = (__half*)smbase;                    // 64 x SHH
    __half* w_s = h_s + 64 * SHH;                     // 32 x SW
    float*  c_s = (float*)(w_s + 32 * SW);            // 8 x 68
    float*  g_s = c_s + 8 * 68;                       // 2 x 32 x 65

    const int tid  = threadIdx.x;
    const int lane = tid & 31;
    const int warp = tid >> 5;
    const int ks   = warp >> 3;        // k half within a 512 slice
    const int wm   = (warp & 7) >> 1;
    const int wn   = warp & 1;

    // ---- preload W as fp16 (resident) -------------------------------------
#pragma unroll
    for (int i = 0; i < WKT / 64; i++) {
        int idx = tid + i * 512;               // 0 .. 32*WKT/4-1
        int r   = idx / (WKT / 4);             // 0..31
        int kq  = (idx % (WKT / 4)) * 4;
        int grow = (r >> 3) * 512 + blk * 8 + (r & 7);
        const float* src;
        if (IS_L1) src = (kq < 512) ? wA + (size_t)grow * 512 + kq
                                    : wB + (size_t)grow * 512 + (kq - 512);
        else       src = wA + (size_t)grow * 512 + kq;
        float4 v = *reinterpret_cast<const float4*>(src);
        __half2* dst = reinterpret_cast<__half2*>(w_s + r * SW + kq);
        dst[0] = __floats2half2_rn(v.x, v.y);
        dst[1] = __floats2half2_rn(v.z, v.w);
    }
    for (int i = tid; i < 8 * 68; i += 512) c_s[i] = 0.0f;

    // epilogue mapping: one (batch, unit) pair per thread
    const int eb   = tid >> 3;
    const int eul  = tid & 7;
    const int ucol = blk * 8 + eul;
    float bia[4] = {0.f, 0.f, 0.f, 0.f};
    if (IS_L1) {
#pragma unroll
        for (int q = 0; q < 4; q++)
            bia[q] = bi[q * 512 + ucol] + bh[q * 512 + ucol];
    }

    // ldmatrix base addresses
    unsigned hbase = (unsigned)__cvta_generic_to_shared(h_s)
                   + (unsigned)(((wm * 16 + (lane & 15)) * SHH
                                 + ks * 256 + ((lane >> 4) << 3)) * 2);
    unsigned wbase = (unsigned)__cvta_generic_to_shared(w_s)
                   + (unsigned)(((wn * 16 + (lane & 15)) * SW
                                 + ks * 256 + ((lane >> 4) << 3)) * 2);

    unsigned* bar0 = &d_bars[0];
    unsigned* bar1 = &d_bars[32];

    __syncthreads();

    for (int t = 0; t < SEQT; t++) {
        float acc0[4] = {0.f, 0.f, 0.f, 0.f};
        float acc1[4] = {0.f, 0.f, 0.f, 0.f};
        float px0 = 0.f, px1 = 0.f, px2 = 0.f, px3 = 0.f;

        if (IS_L1) {
            // ---- self wait (h1[t] ready) + phase A on own data ------------
            if (tid == 0) bar_wait(bar1, 64u * (unsigned)t);
            __syncthreads();
            stage_h(h_s, d_h1seq + (size_t)t * SEQH, tid);
            __syncthreads();
            // phase A: w cols 512..1023 (w_hh1) — overlaps L0's step t
            unsigned cA0[2] = {0u, 0u}, cA1[2] = {0u, 0u};
            mma_phase_h(cA0, cA1, hbase, wbase + 512 * 2);

            // ---- dependency wait on layer-0 step t -------------------------
            if (tid == 0) bar_wait(bar0, 64u * (unsigned)(t + 1));
            __syncthreads();   // also guarantees phase-A LDSMs done
            stage_h(h_s, d_h0seq + (size_t)(t + 1) * SEQH, tid);
            __syncthreads();
            // phase B: w cols 0..511 (w_ih1), separate f16 accumulators
            unsigned cB0[2] = {0u, 0u}, cB1[2] = {0u, 0u};
            mma_phase_h(cB0, cB1, hbase, wbase);

            acc_add(acc0, cA0); acc_add(acc1, cA1);
            acc_add(acc0, cB0); acc_add(acc1, cB1);
        } else {
            // xg prefetch (independent of barrier)
            const float* xp = xg + (size_t)t * (BATCH * G4) + (size_t)eb * G4;
            px0 = xp[ucol];
            px1 = xp[512  + ucol];
            px2 = xp[1024 + ucol];
            px3 = xp[1536 + ucol];

            if (tid == 0) bar_wait(bar0, 64u * (unsigned)t);
            __syncthreads();
            stage_h(h_s, d_h0seq + (size_t)t * SEQH, tid);
            __syncthreads();
            unsigned c0[2] = {0u, 0u}, c1[2] = {0u, 0u};
            mma_phase_h(c0, c1, hbase, wbase);
            acc_add(acc0, c0); acc_add(acc1, c1);
        }

        // ---- stage C frags: g_s[ks][col 0..31][batch 0..63] ----------------
        {
            float* gh = g_s + ks * GH;
            int b  = wm * 16 + (lane >> 2);
            int c0 = wn * 16 + (lane & 3) * 2;
            int c1 = c0 + 8;
            gh[(c0    ) * 65 + b    ] = acc0[0];
            gh[(c0 + 1) * 65 + b    ] = acc0[1];
            gh[(c0    ) * 65 + b + 8] = acc0[2];
            gh[(c0 + 1) * 65 + b + 8] = acc0[3];
            gh[(c1    ) * 65 + b    ] = acc1[0];
            gh[(c1 + 1) * 65 + b    ] = acc1[1];
            gh[(c1    ) * 65 + b + 8] = acc1[2];
            gh[(c1 + 1) * 65 + b + 8] = acc1[3];
        }
        __syncthreads();

        // ---- gates + cell update -------------------------------------------
        {
            float gi = g_s[( 0 + eul) * 65 + eb] + g_s[GH + ( 0 + eul) * 65 + eb];
            float gf = g_s[( 8 + eul) * 65 + eb] + g_s[GH + ( 8 + eul) * 65 + eb];
            float gg = g_s[(16 + eul) * 65 + eb] + g_s[GH + (16 + eul) * 65 + eb];
            float go = g_s[(24 + eul) * 65 + eb] + g_s[GH + (24 + eul) * 65 + eb];
            if (IS_L1) {
                gi += bia[0]; gf += bia[1]; gg += bia[2]; go += bia[3];
            } else {
                gi += px0; gf += px1; gg += px2; go += px3;
            }

            float i_t = sigm_f(gi);
            float f_t = sigm_f(gf);
            float g_t = tanh_f(gg);
            float o_t = sigm_f(go);

            float cn = f_t * c_s[eul * 68 + eb] + i_t * g_t;
            c_s[eul * 68 + eb] = cn;
            float hv = o_t * tanh_f(cn);
            __half* own = IS_L1 ? d_h1seq : d_h0seq;
            own[(size_t)(t + 1) * SEQH + eb * 512 + ucol] = __float2half(hv);
            if (IS_L1 && t == SEQT - 1)
                d_hlast[eb * 512 + ucol] = hv;
        }
        __syncthreads();
        if (tid == 0) bar_red(IS_L1 ? bar1 : bar0);
    }
}

__global__ __launch_bounds__(512)
void lstm_pipeline(const float* __restrict__ xg0,
                   const float* __restrict__ w_hh0,
                   const float* __restrict__ w_ih1,
                   const float* __restrict__ w_hh1,
                   const float* __restrict__ b_ih1,
                   const float* __restrict__ b_hh1)
{
    extern __shared__ char smbase[];
    if (blockIdx.x < 64) {
        lstm_role<false>(xg0, w_hh0, nullptr, nullptr, nullptr,
                         blockIdx.x, smbase);
    } else {
        lstm_role<true>(nullptr, w_ih1, w_hh1, b_ih1, b_hh1,
                        blockIdx.x - 64, smbase);
    }
}

// L1 smem: 64*520*2 + 32*1032*2 + 8*68*4 + 2*32*65*4 = 151424 B
#define PIPE_SMEM (64 * SHH * 2 + 32 * 1032 * 2 + 8 * 68 * 4 + 2 * 32 * 65 * 4)

// ---------------------------------------------------------------------------
// kernel_launch
// ---------------------------------------------------------------------------
extern "C" void kernel_launch(void* const* d_in, const int* in_sizes, int n_in,
                              void* d_out, int out_size)
{
    const int*   X     = (const int*)  d_in[0];
    const float* emb   = (const float*)d_in[1];
    const float* w_ih0 = (const float*)d_in[2];
    const float* w_hh0 = (const float*)d_in[3];
    const float* b_ih0 = (const float*)d_in[4];
    const float* b_hh0 = (const float*)d_in[5];
    const float* w_ih1 = (const float*)d_in[6];
    const float* w_hh1 = (const float*)d_in[7];
    const float* b_ih1 = (const float*)d_in[8];
    const float* b_hh1 = (const float*)d_in[9];
    const float* Wout  = (const float*)d_in[10];
    const float* bout  = (const float*)d_in[11];
    float* out = (float*)d_out;

    float *xg, *hlast;
    __half *h0s, *h1s;
    cudaGetSymbolAddress((void**)&xg,    d_xg);
    cudaGetSymbolAddress((void**)&h0s,   d_h0seq);
    cudaGetSymbolAddress((void**)&h1s,   d_h1seq);
    cudaGetSymbolAddress((void**)&hlast, d_hlast);

    cudaFuncSetAttribute(lstm_pipeline,
                         cudaFuncAttributeMaxDynamicSharedMemorySize,
                         PIPE_SMEM);

    // 1) zero h_0 slots + barriers
    zero_h<<<32, 256>>>(h0s, h1s, SEQH);
    zero_bar<<<1, 32>>>();

    // 2) xg for layer 0 (embedding gather fused, tf32 mma)
    {
        dim3 grid(G4 / 128, MTOT / 128);
        gemm_mma2<<<grid, 512>>>(emb, w_ih0, xg, b_ih0, b_hh0, X,
                                 MTOT, G4, HIDN);
    }

    // 3) pipelined 2-layer recurrence (phase-split L1, f16-acc HMMA)
    lstm_pipeline<<<128, 512, PIPE_SMEM>>>(xg, w_hh0, w_ih1, w_hh1,
                                           b_ih1, b_hh1);

    // 4) logits = h1_last @ W^T + b  (guarded tf32 mma)
    {
        dim3 grid((NCLS + 127) / 128, 1);
        gemm_mma2<<<grid, 512>>>(hlast, Wout, out, bout, nullptr, nullptr,
                                 BATCH, NCLS, HIDN);
    }
}

// round 14
// speedup vs baseline: 1.1604x; 1.0140x over previous
#include <cuda_runtime.h>
#include <cuda_fp16.h>
#include <cstdint>
#include <cstddef>

// ---------------------------------------------------------------------------
// Problem constants
// ---------------------------------------------------------------------------
#define HIDN   512
#define BATCH  64
#define SEQT   256
#define MTOT   (BATCH * SEQT)       // 16384
#define G4     (4 * HIDN)           // 2048
#define NCLS   50257
#define SEQH   (BATCH * HIDN)       // 32768

// ---------------------------------------------------------------------------
// Static device scratch
// ---------------------------------------------------------------------------
__device__ float  d_xg[(size_t)MTOT * G4];               // layer-0 gate preacts
__device__ __half d_h0seq[(size_t)(SEQT + 1) * SEQH];    // slot 0 = zeros
__device__ __half d_h1seq[(size_t)(SEQT + 1) * SEQH];
__device__ float  d_hlast[SEQH];                         // h1[255] fp32
__device__ unsigned d_bars[64];                          // [0]=bar0, [32]=bar1

__global__ void zero_h(__half* a, __half* b, int n)
{
    for (int i = blockIdx.x * blockDim.x + threadIdx.x; i < n;
         i += gridDim.x * blockDim.x) {
        a[i] = __float2half(0.0f);
        b[i] = __float2half(0.0f);
    }
}

__global__ void zero_bar()
{
    if (threadIdx.x == 0) { d_bars[0] = 0; d_bars[32] = 0; }
}

// ---------------------------------------------------------------------------
// Common helpers
// ---------------------------------------------------------------------------
__device__ __forceinline__ unsigned f2tf(float f)
{
    unsigned u;
    asm("cvt.rna.tf32.f32 %0, %1;" : "=r"(u) : "f"(f));
    return u;
}

__device__ __forceinline__ void mma_tf32(float* c, unsigned a0, unsigned a1,
                                         unsigned a2, unsigned a3,
                                         unsigned b0, unsigned b1)
{
    asm volatile(
        "mma.sync.aligned.m16n8k8.row.col.f32.tf32.tf32.f32 "
        "{%0,%1,%2,%3}, {%4,%5,%6,%7}, {%8,%9}, {%0,%1,%2,%3};\n"
        : "+f"(c[0]), "+f"(c[1]), "+f"(c[2]), "+f"(c[3])
        : "r"(a0), "r"(a1), "r"(a2), "r"(a3), "r"(b0), "r"(b1));
}

#define LDSM4(r0, r1, r2, r3, addr)                                        \
    asm volatile("ldmatrix.sync.aligned.m8n8.x4.shared.b16 "               \
                 "{%0,%1,%2,%3}, [%4];"                                    \
                 : "=r"(r0), "=r"(r1), "=r"(r2), "=r"(r3) : "r"(addr))

// fp16-accumulator HMMA (2x rate vs f32-acc on the legacy tensor path).
#define MMA16816H(c, a0, a1, a2, a3, b0, b1)                               \
    asm volatile("mma.sync.aligned.m16n8k16.row.col.f16.f16.f16.f16 "      \
                 "{%0,%1}, {%2,%3,%4,%5}, {%6,%7}, {%0,%1};"               \
                 : "+r"((c)[0]), "+r"((c)[1])                              \
                 : "r"(a0), "r"(a1), "r"(a2), "r"(a3), "r"(b0), "r"(b1))

__device__ __forceinline__ float sigm_f(float x)
{
    return __fdividef(1.0f, 1.0f + __expf(-x));
}

__device__ __forceinline__ float tanh_f(float x)
{
    float e = __expf(2.0f * fabsf(x));
    float r = 1.0f - __fdividef(2.0f, e + 1.0f);
    return copysignf(r, x);
}

// ---------------------------------------------------------------------------
// tf32 mma GEMM, 128x128 tile, 512 threads (16 warps, 4x4), warp tile 32x32.
//   C[m][n] = sum_k A'[m][k]*B[n][k] + bias1[n] (+ bias2[n])
//   Optional embedding row gather on A. Full M/N guards. K multiple of 16.
// ---------------------------------------------------------------------------
__global__ __launch_bounds__(512)
void gemm_mma2(const float* __restrict__ A, const float* __restrict__ B,
               float* __restrict__ C,
               const float* __restrict__ bias1, const float* __restrict__ bias2,
               const int* __restrict__ gX,
               int M, int N, int K)
{
    __shared__ unsigned As[128 * 20];
    __shared__ unsigned Bs[128 * 20];

    const int tid  = threadIdx.x;
    const int lane = tid & 31;
    const int warp = tid >> 5;
    const int wm   = warp >> 2;
    const int wn   = warp & 3;
    const int gid  = lane >> 2;
    const int tig  = lane & 3;
    const int m0   = blockIdx.y * 128;
    const int n0   = blockIdx.x * 128;

    const int lrow = tid >> 2;
    const int lkq  = (tid & 3) * 4;

    const float* Ap;
    {
        int am = m0 + lrow;
        long long r;
        if (gX)          r = gX[(am & 63) * SEQT + (am >> 6)];
        else if (am < M) r = am;
        else             r = 0;
        Ap = A + (size_t)r * K + lkq;
    }
    const float* Bp;
    {
        int bn = n0 + lrow;
        Bp = B + (size_t)(bn < N ? bn : 0) * K + lkq;
    }

    float acc[2][4][4];
#pragma unroll
    for (int a = 0; a < 2; a++)
#pragma unroll
        for (int b = 0; b < 4; b++)
#pragma unroll
            for (int c = 0; c < 4; c++) acc[a][b][c] = 0.0f;

    for (int k0 = 0; k0 < K; k0 += 16) {
        float4 av = *reinterpret_cast<const float4*>(Ap + k0);
        float4 bv = *reinterpret_cast<const float4*>(Bp + k0);

        __syncthreads();
        {
            uint4 ta = make_uint4(f2tf(av.x), f2tf(av.y), f2tf(av.z), f2tf(av.w));
            uint4 tb = make_uint4(f2tf(bv.x), f2tf(bv.y), f2tf(bv.z), f2tf(bv.w));
            *reinterpret_cast<uint4*>(&As[lrow * 20 + lkq]) = ta;
            *reinterpret_cast<uint4*>(&Bs[lrow * 20 + lkq]) = tb;
        }
        __syncthreads();

#pragma unroll
        for (int kk = 0; kk < 16; kk += 8) {
            unsigned afr[2][4];
#pragma unroll
            for (int mi = 0; mi < 2; mi++) {
                int base = (wm * 32 + mi * 16 + gid) * 20 + kk + tig;
                afr[mi][0] = As[base];
                afr[mi][1] = As[base + 8 * 20];
                afr[mi][2] = As[base + 4];
                afr[mi][3] = As[base + 8 * 20 + 4];
            }
#pragma unroll
            for (int ni = 0; ni < 4; ni++) {
                int nb = (wn * 32 + ni * 8 + gid) * 20 + kk + tig;
                unsigned b0 = Bs[nb];
                unsigned b1 = Bs[nb + 4];
                mma_tf32(acc[0][ni], afr[0][0], afr[0][1], afr[0][2], afr[0][3], b0, b1);
                mma_tf32(acc[1][ni], afr[1][0], afr[1][1], afr[1][2], afr[1][3], b0, b1);
            }
        }
    }

#pragma unroll
    for (int ni = 0; ni < 4; ni++) {
        int col = n0 + wn * 32 + ni * 8 + 2 * tig;
        float bs0 = 0.f, bs1 = 0.f;
        if (col < N)     bs0 = bias1[col]     + (bias2 ? bias2[col]     : 0.0f);
        if (col + 1 < N) bs1 = bias1[col + 1] + (bias2 ? bias2[col + 1] : 0.0f);
#pragma unroll
        for (int mi = 0; mi < 2; mi++) {
            int row = m0 + wm * 32 + mi * 16 + gid;
#pragma unroll
            for (int rr = 0; rr < 2; rr++) {
                int r = row + rr * 8;
                if (r < M) {
                    if (col < N)
                        C[(size_t)r * N + col]     = acc[mi][ni][rr * 2]     + bs0;
                    if (col + 1 < N)
                        C[(size_t)r * N + col + 1] = acc[mi][ni][rr * 2 + 1] + bs1;
                }
            }
        }
    }
}

// ---------------------------------------------------------------------------
// Pipelined persistent LSTM, f16-acc HMMA, L1 tick reordered so that ONLY the
// h1 self-dependency sits on the critical loop:
//   Blocks 0-63:  layer-0. g = h0_{t-1} @ w_hh0^T + xg0[t]   (k=512)
//   Blocks 64-127: layer-1.
//     step 1: wait bar0(t+1)  [L0 runs ahead -> nearly free]
//     step 2: stage h0[t+1], phase B = h0 @ w_ih1^T  (off self-loop)
//     step 3: wait bar1(t)    [the real self-dependency]
//     step 4: stage h1[t], phase A = h1 @ w_hh1^T
//     step 5: combine fp32, gates, publish h1[t+1], bar1 red
// Block owns 8 hidden units (32 gate cols). f16 accumulator chains capped at
// 16 HMMA; phases and k-halves reduced in fp32.
// ---------------------------------------------------------------------------
#define GH   (32 * 65)
#define SHH  520                       // h buffer stride (halfs)

// stage one 512-wide fp16 h slice [64][512] -> h_s (stride SHH)
__device__ __forceinline__ void stage_h(__half* h_s, const __half* src, int tid)
{
    const uint4* s = (const uint4*)src;
#pragma unroll
    for (int i = 0; i < 8; i++) {
        int idx = tid + i * 512;
        int b = idx >> 6, kc = idx & 63;
        uint4 v = s[b * 64 + kc];
        *reinterpret_cast<uint4*>(h_s + b * SHH + kc * 8) = v;
    }
}

// one 256-k phase with f16 accumulation (16 chained HMMA per accumulator)
__device__ __forceinline__ void mma_phase_h(unsigned* c0, unsigned* c1,
                                            unsigned hbase, unsigned wphase)
{
#pragma unroll
    for (int kk = 0; kk < 16; kk++) {
        unsigned ra0, ra1, ra2, ra3, rb0, rb1, rb2, rb3;
        LDSM4(ra0, ra1, ra2, ra3, hbase + kk * 32);
        LDSM4(rb0, rb1, rb2, rb3, wphase + kk * 32);
        MMA16816H(c0, ra0, ra1, ra2, ra3, rb0, rb2);
        MMA16816H(c1, ra0, ra1, ra2, ra3, rb1, rb3);
    }
}

// unpack f16x4 accumulator and add into fp32 accumulator
__device__ __forceinline__ void acc_add(float* f, const unsigned* c)
{
    __half2 h0 = *reinterpret_cast<const __half2*>(&c[0]);
    __half2 h1 = *reinterpret_cast<const __half2*>(&c[1]);
    float2 f0 = __half22float2(h0);
    float2 f1 = __half22float2(h1);
    f[0] += f0.x; f[1] += f0.y; f[2] += f1.x; f[3] += f1.y;
}

__device__ __forceinline__ void bar_red(unsigned* bar)
{
    asm volatile("red.release.gpu.global.add.u32 [%0], %1;"
                 :: "l"(bar), "r"(1u) : "memory");
}

__device__ __forceinline__ void bar_wait(unsigned* bar, unsigned target)
{
    unsigned v;
    do {
        asm volatile("ld.acquire.gpu.global.u32 %0, [%1];"
                     : "=r"(v) : "l"(bar) : "memory");
    } while (v < target);
}

template<bool IS_L1>
__device__ __forceinline__ void lstm_role(
    const float* __restrict__ xg,      // L0 only
    const float* __restrict__ wA,      // L0: w_hh0 ; L1: w_ih1
    const float* __restrict__ wB,      // L1: w_hh1
    const float* __restrict__ bi,      // L1: b_ih1
    const float* __restrict__ bh,      // L1: b_hh1
    int blk, char* smbase)
{
    constexpr int WKT = IS_L1 ? 1024 : 512;   // weight k extent
    constexpr int SW  = WKT + 8;              // w row stride (halfs)

    __half* h_s = (__half*)smbase;                    // 64 x SHH
    __half* w_s = h_s + 64 * SHH;                     // 32 x SW
    float*  c_s = (float*)(w_s + 32 * SW);            // 8 x 68
    float*  g_s = c_s + 8 * 68;                       // 2 x 32 x 65

    const int tid  = threadIdx.x;
    const int lane = tid & 31;
    const int warp = tid >> 5;
    const int ks   = warp >> 3;        // k half within a 512 slice
    const int wm   = (warp & 7) >> 1;
    const int wn   = warp & 1;

    // ---- preload W as fp16 (resident) -------------------------------------
#pragma unroll
    for (int i = 0; i < WKT / 64; i++) {
        int idx = tid + i * 512;               // 0 .. 32*WKT/4-1
        int r   = idx / (WKT / 4);             // 0..31
        int kq  = (idx % (WKT / 4)) * 4;
        int grow = (r >> 3) * 512 + blk * 8 + (r & 7);
        const float* src;
        if (IS_L1) src = (kq < 512) ? wA + (size_t)grow * 512 + kq
                                    : wB + (size_t)grow * 512 + (kq - 512);
        else       src = wA + (size_t)grow * 512 + kq;
        float4 v = *reinterpret_cast<const float4*>(src);
        __half2* dst = reinterpret_cast<__half2*>(w_s + r * SW + kq);
        dst[0] = __floats2half2_rn(v.x, v.y);
        dst[1] = __floats2half2_rn(v.z, v.w);
    }
    for (int i = tid; i < 8 * 68; i += 512) c_s[i] = 0.0f;

    // epilogue mapping: one (batch, unit) pair per thread
    const int eb   = tid >> 3;
    const int eul  = tid & 7;
    const int ucol = blk * 8 + eul;
    float bia[4] = {0.f, 0.f, 0.f, 0.f};
    if (IS_L1) {
#pragma unroll
        for (int q = 0; q < 4; q++)
            bia[q] = bi[q * 512 + ucol] + bh[q * 512 + ucol];
    }

    // ldmatrix base addresses
    unsigned hbase = (unsigned)__cvta_generic_to_shared(h_s)
                   + (unsigned)(((wm * 16 + (lane & 15)) * SHH
                                 + ks * 256 + ((lane >> 4) << 3)) * 2);
    unsigned wbase = (unsigned)__cvta_generic_to_shared(w_s)
                   + (unsigned)(((wn * 16 + (lane & 15)) * SW
                                 + ks * 256 + ((lane >> 4) << 3)) * 2);

    unsigned* bar0 = &d_bars[0];
    unsigned* bar1 = &d_bars[32];

    __syncthreads();

    for (int t = 0; t < SEQT; t++) {
        float acc0[4] = {0.f, 0.f, 0.f, 0.f};
        float acc1[4] = {0.f, 0.f, 0.f, 0.f};
        float px0 = 0.f, px1 = 0.f, px2 = 0.f, px3 = 0.f;

        if (IS_L1) {
            // ---- step 1+2: h0-dependent half FIRST (L0 runs ahead) ---------
            if (tid == 0) bar_wait(bar0, 64u * (unsigned)(t + 1));
            __syncthreads();
            stage_h(h_s, d_h0seq + (size_t)(t + 1) * SEQH, tid);
            __syncthreads();
            // phase B: w cols 0..511 (w_ih1) into dedicated f16 accumulators
            unsigned cB0[2] = {0u, 0u}, cB1[2] = {0u, 0u};
            mma_phase_h(cB0, cB1, hbase, wbase);

            // ---- step 3: the REAL self-dependency wait ---------------------
            if (tid == 0) bar_wait(bar1, 64u * (unsigned)t);
            __syncthreads();   // also guarantees phase-B LDSMs done
            stage_h(h_s, d_h1seq + (size_t)t * SEQH, tid);
            __syncthreads();
            // phase A: w cols 512..1023 (w_hh1)
            unsigned cA0[2] = {0u, 0u}, cA1[2] = {0u, 0u};
            mma_phase_h(cA0, cA1, hbase, wbase + 512 * 2);

            acc_add(acc0, cA0); acc_add(acc1, cA1);
            acc_add(acc0, cB0); acc_add(acc1, cB1);
        } else {
            // xg prefetch (independent of barrier)
            const float* xp = xg + (size_t)t * (BATCH * G4) + (size_t)eb * G4;
            px0 = xp[ucol];
            px1 = xp[512  + ucol];
            px2 = xp[1024 + ucol];
            px3 = xp[1536 + ucol];

            if (tid == 0) bar_wait(bar0, 64u * (unsigned)t);
            __syncthreads();
            stage_h(h_s, d_h0seq + (size_t)t * SEQH, tid);
            __syncthreads();
            unsigned c0[2] = {0u, 0u}, c1[2] = {0u, 0u};
            mma_phase_h(c0, c1, hbase, wbase);
            acc_add(acc0, c0); acc_add(acc1, c1);
        }

        // ---- stage C frags: g_s[ks][col 0..31][batch 0..63] ----------------
        {
            float* gh = g_s + ks * GH;
            int b  = wm * 16 + (lane >> 2);
            int c0 = wn * 16 + (lane & 3) * 2;
            int c1 = c0 + 8;
            gh[(c0    ) * 65 + b    ] = acc0[0];
            gh[(c0 + 1) * 65 + b    ] = acc0[1];
            gh[(c0    ) * 65 + b + 8] = acc0[2];
            gh[(c0 + 1) * 65 + b + 8] = acc0[3];
            gh[(c1    ) * 65 + b    ] = acc1[0];
            gh[(c1 + 1) * 65 + b    ] = acc1[1];
            gh[(c1    ) * 65 + b + 8] = acc1[2];
            gh[(c1 + 1) * 65 + b + 8] = acc1[3];
        }
        __syncthreads();

        // ---- gates + cell update -------------------------------------------
        {
            float gi = g_s[( 0 + eul) * 65 + eb] + g_s[GH + ( 0 + eul) * 65 + eb];
            float gf = g_s[( 8 + eul) * 65 + eb] + g_s[GH + ( 8 + eul) * 65 + eb];
            float gg = g_s[(16 + eul) * 65 + eb] + g_s[GH + (16 + eul) * 65 + eb];
            float go = g_s[(24 + eul) * 65 + eb] + g_s[GH + (24 + eul) * 65 + eb];
            if (IS_L1) {
                gi += bia[0]; gf += bia[1]; gg += bia[2]; go += bia[3];
            } else {
                gi += px0; gf += px1; gg += px2; go += px3;
            }

            float i_t = sigm_f(gi);
            float f_t = sigm_f(gf);
            float g_t = tanh_f(gg);
            float o_t = sigm_f(go);

            float cn = f_t * c_s[eul * 68 + eb] + i_t * g_t;
            c_s[eul * 68 + eb] = cn;
            float hv = o_t * tanh_f(cn);
            __half* own = IS_L1 ? d_h1seq : d_h0seq;
            own[(size_t)(t + 1) * SEQH + eb * 512 + ucol] = __float2half(hv);
            if (IS_L1 && t == SEQT - 1)
                d_hlast[eb * 512 + ucol] = hv;
        }
        __syncthreads();
        if (tid == 0) bar_red(IS_L1 ? bar1 : bar0);
    }
}

__global__ __launch_bounds__(512)
void lstm_pipeline(const float* __restrict__ xg0,
                   const float* __restrict__ w_hh0,
                   const float* __restrict__ w_ih1,
                   const float* __restrict__ w_hh1,
                   const float* __restrict__ b_ih1,
                   const float* __restrict__ b_hh1)
{
    extern __shared__ char smbase[];
    if (blockIdx.x < 64) {
        lstm_role<false>(xg0, w_hh0, nullptr, nullptr, nullptr,
                         blockIdx.x, smbase);
    } else {
        lstm_role<true>(nullptr, w_ih1, w_hh1, b_ih1, b_hh1,
                        blockIdx.x - 64, smbase);
    }
}

// L1 smem: 64*520*2 + 32*1032*2 + 8*68*4 + 2*32*65*4 = 151424 B
#define PIPE_SMEM (64 * SHH * 2 + 32 * 1032 * 2 + 8 * 68 * 4 + 2 * 32 * 65 * 4)

// ---------------------------------------------------------------------------
// kernel_launch
// ---------------------------------------------------------------------------
extern "C" void kernel_launch(void* const* d_in, const int* in_sizes, int n_in,
                              void* d_out, int out_size)
{
    const int*   X     = (const int*)  d_in[0];
    const float* emb   = (const float*)d_in[1];
    const float* w_ih0 = (const float*)d_in[2];
    const float* w_hh0 = (const float*)d_in[3];
    const float* b_ih0 = (const float*)d_in[4];
    const float* b_hh0 = (const float*)d_in[5];
    const float* w_ih1 = (const float*)d_in[6];
    const float* w_hh1 = (const float*)d_in[7];
    const float* b_ih1 = (const float*)d_in[8];
    const float* b_hh1 = (const float*)d_in[9];
    const float* Wout  = (const float*)d_in[10];
    const float* bout  = (const float*)d_in[11];
    float* out = (float*)d_out;

    float *xg, *hlast;
    __half *h0s, *h1s;
    cudaGetSymbolAddress((void**)&xg,    d_xg);
    cudaGetSymbolAddress((void**)&h0s,   d_h0seq);
    cudaGetSymbolAddress((void**)&h1s,   d_h1seq);
    cudaGetSymbolAddress((void**)&hlast, d_hlast);

    cudaFuncSetAttribute(lstm_pipeline,
                         cudaFuncAttributeMaxDynamicSharedMemorySize,
                         PIPE_SMEM);

    // 1) zero h_0 slots + barriers
    zero_h<<<32, 256>>>(h0s, h1s, SEQH);
    zero_bar<<<1, 32>>>();

    // 2) xg for layer 0 (embedding gather fused, tf32 mma)
    {
        dim3 grid(G4 / 128, MTOT / 128);
        gemm_mma2<<<grid, 512>>>(emb, w_ih0, xg, b_ih0, b_hh0, X,
                                 MTOT, G4, HIDN);
    }

    // 3) pipelined 2-layer recurrence (L1 critical loop = h1 half only)
    lstm_pipeline<<<128, 512, PIPE_SMEM>>>(xg, w_hh0, w_ih1, w_hh1,
                                           b_ih1, b_hh1);

    // 4) logits = h1_last @ W^T + b  (guarded tf32 mma)
    {
        dim3 grid((NCLS + 127) / 128, 1);
        gemm_mma2<<<grid, 512>>>(hlast, Wout, out, bout, nullptr, nullptr,
                                 BATCH, NCLS, HIDN);
    }
}

// round 15
// speedup vs baseline: 1.3496x; 1.1631x over previous
#include <cuda_runtime.h>
#include <cuda_fp16.h>
#include <cstdint>
#include <cstddef>

// ---------------------------------------------------------------------------
// Problem constants
// ---------------------------------------------------------------------------
#define HIDN   512
#define BATCH  64
#define SEQT   256
#define MTOT   (BATCH * SEQT)       // 16384
#define G4     (4 * HIDN)           // 2048
#define NCLS   50257
#define SEQH   (BATCH * HIDN)       // 32768

// ---------------------------------------------------------------------------
// Static device scratch
// ---------------------------------------------------------------------------
__device__ float  d_xg[(size_t)MTOT * G4];               // layer-0 gate preacts
__device__ __half d_h0seq[(size_t)(SEQT + 1) * SEQH];    // slot 0 = zeros
__device__ __half d_h1seq[(size_t)(SEQT + 1) * SEQH];
__device__ float  d_hlast[SEQH];                         // h1[255] fp32
__device__ unsigned d_bars[64];                          // [0]=bar0, [32]=bar1

__global__ void zero_h(__half* a, __half* b, int n)
{
    for (int i = blockIdx.x * blockDim.x + threadIdx.x; i < n;
         i += gridDim.x * blockDim.x) {
        a[i] = __float2half(0.0f);
        b[i] = __float2half(0.0f);
    }
}

__global__ void zero_bar()
{
    if (threadIdx.x == 0) { d_bars[0] = 0; d_bars[32] = 0; }
}

// ---------------------------------------------------------------------------
// Common helpers
// ---------------------------------------------------------------------------
__device__ __forceinline__ unsigned f2tf(float f)
{
    unsigned u;
    asm("cvt.rna.tf32.f32 %0, %1;" : "=r"(u) : "f"(f));
    return u;
}

__device__ __forceinline__ void mma_tf32(float* c, unsigned a0, unsigned a1,
                                         unsigned a2, unsigned a3,
                                         unsigned b0, unsigned b1)
{
    asm volatile(
        "mma.sync.aligned.m16n8k8.row.col.f32.tf32.tf32.f32 "
        "{%0,%1,%2,%3}, {%4,%5,%6,%7}, {%8,%9}, {%0,%1,%2,%3};\n"
        : "+f"(c[0]), "+f"(c[1]), "+f"(c[2]), "+f"(c[3])
        : "r"(a0), "r"(a1), "r"(a2), "r"(a3), "r"(b0), "r"(b1));
}

#define LDSM4(r0, r1, r2, r3, addr)                                        \
    asm volatile("ldmatrix.sync.aligned.m8n8.x4.shared.b16 "               \
                 "{%0,%1,%2,%3}, [%4];"                                    \
                 : "=r"(r0), "=r"(r1), "=r"(r2), "=r"(r3) : "r"(addr))

// fp16-accumulator HMMA (2x rate vs f32-acc on the legacy tensor path).
#define MMA16816H(c, a0, a1, a2, a3, b0, b1)                               \
    asm volatile("mma.sync.aligned.m16n8k16.row.col.f16.f16.f16.f16 "      \
                 "{%0,%1}, {%2,%3,%4,%5}, {%6,%7}, {%0,%1};"               \
                 : "+r"((c)[0]), "+r"((c)[1])                              \
                 : "r"(a0), "r"(a1), "r"(a2), "r"(a3), "r"(b0), "r"(b1))

#define BARN(id, n)                                                        \
    asm volatile("bar.sync %0, %1;" :: "r"(id), "r"(n) : "memory")

__device__ __forceinline__ float sigm_f(float x)
{
    return __fdividef(1.0f, 1.0f + __expf(-x));
}

__device__ __forceinline__ float tanh_f(float x)
{
    float e = __expf(2.0f * fabsf(x));
    float r = 1.0f - __fdividef(2.0f, e + 1.0f);
    return copysignf(r, x);
}

// ---------------------------------------------------------------------------
// tf32 mma GEMM, 128x128 tile, 512 threads (16 warps, 4x4), warp tile 32x32.
//   C[m][n] = sum_k A'[m][k]*B[n][k] + bias1[n] (+ bias2[n])
//   Optional embedding row gather on A. Full M/N guards. K multiple of 16.
// ---------------------------------------------------------------------------
__global__ __launch_bounds__(512)
void gemm_mma2(const float* __restrict__ A, const float* __restrict__ B,
               float* __restrict__ C,
               const float* __restrict__ bias1, const float* __restrict__ bias2,
               const int* __restrict__ gX,
               int M, int N, int K)
{
    __shared__ unsigned As[128 * 20];
    __shared__ unsigned Bs[128 * 20];

    const int tid  = threadIdx.x;
    const int lane = tid & 31;
    const int warp = tid >> 5;
    const int wm   = warp >> 2;
    const int wn   = warp & 3;
    const int gid  = lane >> 2;
    const int tig  = lane & 3;
    const int m0   = blockIdx.y * 128;
    const int n0   = blockIdx.x * 128;

    const int lrow = tid >> 2;
    const int lkq  = (tid & 3) * 4;

    const float* Ap;
    {
        int am = m0 + lrow;
        long long r;
        if (gX)          r = gX[(am & 63) * SEQT + (am >> 6)];
        else if (am < M) r = am;
        else             r = 0;
        Ap = A + (size_t)r * K + lkq;
    }
    const float* Bp;
    {
        int bn = n0 + lrow;
        Bp = B + (size_t)(bn < N ? bn : 0) * K + lkq;
    }

    float acc[2][4][4];
#pragma unroll
    for (int a = 0; a < 2; a++)
#pragma unroll
        for (int b = 0; b < 4; b++)
#pragma unroll
            for (int c = 0; c < 4; c++) acc[a][b][c] = 0.0f;

    for (int k0 = 0; k0 < K; k0 += 16) {
        float4 av = *reinterpret_cast<const float4*>(Ap + k0);
        float4 bv = *reinterpret_cast<const float4*>(Bp + k0);

        __syncthreads();
        {
            uint4 ta = make_uint4(f2tf(av.x), f2tf(av.y), f2tf(av.z), f2tf(av.w));
            uint4 tb = make_uint4(f2tf(bv.x), f2tf(bv.y), f2tf(bv.z), f2tf(bv.w));
            *reinterpret_cast<uint4*>(&As[lrow * 20 + lkq]) = ta;
            *reinterpret_cast<uint4*>(&Bs[lrow * 20 + lkq]) = tb;
        }
        __syncthreads();

#pragma unroll
        for (int kk = 0; kk < 16; kk += 8) {
            unsigned afr[2][4];
#pragma unroll
            for (int mi = 0; mi < 2; mi++) {
                int base = (wm * 32 + mi * 16 + gid) * 20 + kk + tig;
                afr[mi][0] = As[base];
                afr[mi][1] = As[base + 8 * 20];
                afr[mi][2] = As[base + 4];
                afr[mi][3] = As[base + 8 * 20 + 4];
            }
#pragma unroll
            for (int ni = 0; ni < 4; ni++) {
                int nb = (wn * 32 + ni * 8 + gid) * 20 + kk + tig;
                unsigned b0 = Bs[nb];
                unsigned b1 = Bs[nb + 4];
                mma_tf32(acc[0][ni], afr[0][0], afr[0][1], afr[0][2], afr[0][3], b0, b1);
                mma_tf32(acc[1][ni], afr[1][0], afr[1][1], afr[1][2], afr[1][3], b0, b1);
            }
        }
    }

#pragma unroll
    for (int ni = 0; ni < 4; ni++) {
        int col = n0 + wn * 32 + ni * 8 + 2 * tig;
        float bs0 = 0.f, bs1 = 0.f;
        if (col < N)     bs0 = bias1[col]     + (bias2 ? bias2[col]     : 0.0f);
        if (col + 1 < N) bs1 = bias1[col + 1] + (bias2 ? bias2[col + 1] : 0.0f);
#pragma unroll
        for (int mi = 0; mi < 2; mi++) {
            int row = m0 + wm * 32 + mi * 16 + gid;
#pragma unroll
            for (int rr = 0; rr < 2; rr++) {
                int r = row + rr * 8;
                if (r < M) {
                    if (col < N)
                        C[(size_t)r * N + col]     = acc[mi][ni][rr * 2]     + bs0;
                    if (col + 1 < N)
                        C[(size_t)r * N + col + 1] = acc[mi][ni][rr * 2 + 1] + bs1;
                }
            }
        }
    }
}

// ---------------------------------------------------------------------------
// Pipelined persistent LSTM, warp-specialized L1.
//   Blocks 0-63 (L0, 16 warps): g = h0_{t-1} @ w_hh0^T + xg0[t]   (k=512)
//   Blocks 64-127 (L1):
//     Group A (warps 0-7):  poll bar1 -> stage h1[t]   -> h1 @ w_hh1^T
//     Group B (warps 8-15): poll bar0 -> stage h0[t+1] -> h0 @ w_ih1^T
//     (concurrent; meet at one __syncthreads, then shared epilogue)
// Block owns 8 hidden units (32 gate cols). f16 accumulator chains capped
// at 16 HMMA; chains and groups reduced in fp32 via g_s.
// ---------------------------------------------------------------------------
#define GH   (32 * 65)
#define SHH  520                       // h buffer stride (halfs)

// stage one 512-wide fp16 h slice [64][512] with 512 threads (L0)
__device__ __forceinline__ void stage_h512(__half* h_s, const __half* src,
                                           int tid)
{
    const uint4* s = (const uint4*)src;
#pragma unroll
    for (int i = 0; i < 8; i++) {
        int idx = tid + i * 512;
        int b = idx >> 6, kc = idx & 63;
        uint4 v = s[b * 64 + kc];
        *reinterpret_cast<uint4*>(h_s + b * SHH + kc * 8) = v;
    }
}

// stage one 512-wide fp16 h slice with 256 threads (L1 warp groups)
__device__ __forceinline__ void stage_h256(__half* h_s, const __half* src,
                                           int tid2)
{
    const uint4* s = (const uint4*)src;
#pragma unroll
    for (int i = 0; i < 16; i++) {
        int idx = tid2 + i * 256;
        int b = idx >> 6, kc = idx & 63;
        uint4 v = s[b * 64 + kc];
        *reinterpret_cast<uint4*>(h_s + b * SHH + kc * 8) = v;
    }
}

// 256-k phase, f16 acc chains of 16 (used by L0, 16 warps with ks split)
__device__ __forceinline__ void mma_phase16(unsigned* c0, unsigned* c1,
                                            unsigned hbase, unsigned wbase)
{
#pragma unroll
    for (int kk = 0; kk < 16; kk++) {
        unsigned ra0, ra1, ra2, ra3, rb0, rb1, rb2, rb3;
        LDSM4(ra0, ra1, ra2, ra3, hbase + kk * 32);
        LDSM4(rb0, rb1, rb2, rb3, wbase + kk * 32);
        MMA16816H(c0, ra0, ra1, ra2, ra3, rb0, rb2);
        MMA16816H(c1, ra0, ra1, ra2, ra3, rb1, rb3);
    }
}

// unpack f16x4 accumulator and add into fp32 accumulator
__device__ __forceinline__ void acc_add(float* f, const unsigned* c)
{
    __half2 h0 = *reinterpret_cast<const __half2*>(&c[0]);
    __half2 h1 = *reinterpret_cast<const __half2*>(&c[1]);
    float2 f0 = __half22float2(h0);
    float2 f1 = __half22float2(h1);
    f[0] += f0.x; f[1] += f0.y; f[2] += f1.x; f[3] += f1.y;
}

// 512-k phase as two 16-chains merged in fp32 (L1 groups, 8 warps each)
__device__ __forceinline__ void mma_phase32(float* a0, float* a1,
                                            unsigned hbase, unsigned wbase)
{
    unsigned cX0[2] = {0u, 0u}, cX1[2] = {0u, 0u};
    mma_phase16(cX0, cX1, hbase, wbase);
    unsigned cY0[2] = {0u, 0u}, cY1[2] = {0u, 0u};
    mma_phase16(cY0, cY1, hbase + 16 * 32, wbase + 16 * 32);
    acc_add(a0, cX0); acc_add(a0, cY0);
    acc_add(a1, cX1); acc_add(a1, cY1);
}

__device__ __forceinline__ void bar_red(unsigned* bar)
{
    asm volatile("red.release.gpu.global.add.u32 [%0], %1;"
                 :: "l"(bar), "r"(1u) : "memory");
}

__device__ __forceinline__ void bar_wait(unsigned* bar, unsigned target)
{
    unsigned v;
    do {
        asm volatile("ld.acquire.gpu.global.u32 %0, [%1];"
                     : "=r"(v) : "l"(bar) : "memory");
    } while (v < target);
}

template<bool IS_L1>
__device__ __forceinline__ void lstm_role(
    const float* __restrict__ xg,      // L0 only
    const float* __restrict__ wA,      // L0: w_hh0 ; L1: w_ih1
    const float* __restrict__ wB,      // L1: w_hh1
    const float* __restrict__ bi,      // L1: b_ih1
    const float* __restrict__ bh,      // L1: b_hh1
    int blk, char* smbase)
{
    constexpr int WKT = IS_L1 ? 1024 : 512;   // weight k extent
    constexpr int SW  = WKT + 8;              // w row stride (halfs)
    constexpr int NHB = IS_L1 ? 2 : 1;        // h staging buffers

    __half* h_s  = (__half*)smbase;                   // buf0: L0 h0 / L1 h1
    __half* h0_s = h_s + 64 * SHH;                    // L1 only: h0 buffer
    __half* w_s  = h_s + NHB * 64 * SHH;              // 32 x SW
    float*  c_s  = (float*)(w_s + 32 * SW);           // 8 x 68
    float*  g_s  = c_s + 8 * 68;                      // 2 x 32 x 65

    const int tid  = threadIdx.x;
    const int lane = tid & 31;
    const int warp = tid >> 5;

    // ---- preload W as fp16 (resident) -------------------------------------
#pragma unroll
    for (int i = 0; i < WKT / 64; i++) {
        int idx = tid + i * 512;               // 0 .. 32*WKT/4-1
        int r   = idx / (WKT / 4);             // 0..31
        int kq  = (idx % (WKT / 4)) * 4;
        int grow = (r >> 3) * 512 + blk * 8 + (r & 7);
        const float* src;
        if (IS_L1) src = (kq < 512) ? wA + (size_t)grow * 512 + kq
                                    : wB + (size_t)grow * 512 + (kq - 512);
        else       src = wA + (size_t)grow * 512 + kq;
        float4 v = *reinterpret_cast<const float4*>(src);
        __half2* dst = reinterpret_cast<__half2*>(w_s + r * SW + kq);
        dst[0] = __floats2half2_rn(v.x, v.y);
        dst[1] = __floats2half2_rn(v.z, v.w);
    }
    for (int i = tid; i < 8 * 68; i += 512) c_s[i] = 0.0f;

    // epilogue mapping: one (batch, unit) pair per thread
    const int eb   = tid >> 3;
    const int eul  = tid & 7;
    const int ucol = blk * 8 + eul;
    float bia[4] = {0.f, 0.f, 0.f, 0.f};
    if (IS_L1) {
#pragma unroll
        for (int q = 0; q < 4; q++)
            bia[q] = bi[q * 512 + ucol] + bh[q * 512 + ucol];
    }

    // ---- per-role warp mappings + ldmatrix bases ---------------------------
    const int k8 = (lane >> 4) << 3;
    unsigned hbase, wbase;
    int gslot;
    if (IS_L1) {
        const int grp = warp >> 3;             // 0 = A (h1), 1 = B (h0)
        const int gw  = warp & 7;
        const int wm  = gw >> 1;               // 0..3
        const int wn  = gw & 1;                // 0..1
        __half* hb = grp ? h0_s : h_s;
        hbase = (unsigned)__cvta_generic_to_shared(hb)
              + (unsigned)(((wm * 16 + (lane & 15)) * SHH + k8) * 2);
        // group A -> w cols 512..1023 (w_hh1); group B -> cols 0..511 (w_ih1)
        wbase = (unsigned)__cvta_generic_to_shared(w_s)
              + (unsigned)(((wn * 16 + (lane & 15)) * SW
                            + (grp ? 0 : 512) + k8) * 2);
        gslot = grp;
    } else {
        const int ks = warp >> 3;
        const int wm = (warp & 7) >> 1;
        const int wn = warp & 1;
        hbase = (unsigned)__cvta_generic_to_shared(h_s)
              + (unsigned)(((wm * 16 + (lane & 15)) * SHH + ks * 256 + k8) * 2);
        wbase = (unsigned)__cvta_generic_to_shared(w_s)
              + (unsigned)(((wn * 16 + (lane & 15)) * SW + ks * 256 + k8) * 2);
        gslot = ks;
    }
    // g_s staging coordinates (same pattern both roles)
    const int gwm = IS_L1 ? ((warp & 7) >> 1) : ((warp & 7) >> 1);
    const int gwn = warp & 1;
    const int gb  = gwm * 16 + (lane >> 2);
    const int gc0 = gwn * 16 + (lane & 3) * 2;

    unsigned* bar0 = &d_bars[0];
    unsigned* bar1 = &d_bars[32];

    __syncthreads();

    for (int t = 0; t < SEQT; t++) {
        float acc0[4] = {0.f, 0.f, 0.f, 0.f};
        float acc1[4] = {0.f, 0.f, 0.f, 0.f};
        float px0 = 0.f, px1 = 0.f, px2 = 0.f, px3 = 0.f;

        if (IS_L1) {
            const int grp  = warp >> 3;
            const int tid2 = tid & 255;
            if (grp == 0) {
                // Group A: the real self-dependency (h1)
                if (tid == 0) bar_wait(bar1, 64u * (unsigned)t);
                BARN(1, 256);
                stage_h256(h_s, d_h1seq + (size_t)t * SEQH, tid2);
                BARN(1, 256);
                mma_phase32(acc0, acc1, hbase, wbase);
            } else {
                // Group B: h0 half (L0 runs ahead -> wait nearly free)
                if (tid == 256) bar_wait(bar0, 64u * (unsigned)(t + 1));
                BARN(2, 256);
                stage_h256(h0_s, d_h0seq + (size_t)(t + 1) * SEQH, tid2);
                BARN(2, 256);
                mma_phase32(acc0, acc1, hbase, wbase);
            }
        } else {
            // xg prefetch (independent of barrier)
            const float* xp = xg + (size_t)t * (BATCH * G4) + (size_t)eb * G4;
            px0 = xp[ucol];
            px1 = xp[512  + ucol];
            px2 = xp[1024 + ucol];
            px3 = xp[1536 + ucol];

            if (tid == 0) bar_wait(bar0, 64u * (unsigned)t);
            __syncthreads();
            stage_h512(h_s, d_h0seq + (size_t)t * SEQH, tid);
            __syncthreads();
            unsigned c0[2] = {0u, 0u}, c1[2] = {0u, 0u};
            mma_phase16(c0, c1, hbase, wbase);
            acc_add(acc0, c0); acc_add(acc1, c1);
        }

        // ---- stage partials: g_s[gslot][col 0..31][batch 0..63] -----------
        {
            float* gh = g_s + gslot * GH;
            int c1 = gc0 + 8;
            gh[(gc0    ) * 65 + gb    ] = acc0[0];
            gh[(gc0 + 1) * 65 + gb    ] = acc0[1];
            gh[(gc0    ) * 65 + gb + 8] = acc0[2];
            gh[(gc0 + 1) * 65 + gb + 8] = acc0[3];
            gh[(c1     ) * 65 + gb    ] = acc1[0];
            gh[(c1  + 1) * 65 + gb    ] = acc1[1];
            gh[(c1     ) * 65 + gb + 8] = acc1[2];
            gh[(c1  + 1) * 65 + gb + 8] = acc1[3];
        }
        __syncthreads();   // groups meet here

        // ---- gates + cell update -------------------------------------------
        {
            float gi = g_s[( 0 + eul) * 65 + eb] + g_s[GH + ( 0 + eul) * 65 + eb];
            float gf = g_s[( 8 + eul) * 65 + eb] + g_s[GH + ( 8 + eul) * 65 + eb];
            float gg = g_s[(16 + eul) * 65 + eb] + g_s[GH + (16 + eul) * 65 + eb];
            float go = g_s[(24 + eul) * 65 + eb] + g_s[GH + (24 + eul) * 65 + eb];
            if (IS_L1) {
                gi += bia[0]; gf += bia[1]; gg += bia[2]; go += bia[3];
            } else {
                gi += px0; gf += px1; gg += px2; go += px3;
            }

            float i_t = sigm_f(gi);
            float f_t = sigm_f(gf);
            float g_t = tanh_f(gg);
            float o_t = sigm_f(go);

            float cn = f_t * c_s[eul * 68 + eb] + i_t * g_t;
            c_s[eul * 68 + eb] = cn;
            float hv = o_t * tanh_f(cn);
            __half* own = IS_L1 ? d_h1seq : d_h0seq;
            own[(size_t)(t + 1) * SEQH + eb * 512 + ucol] = __float2half(hv);
            if (IS_L1 && t == SEQT - 1)
                d_hlast[eb * 512 + ucol] = hv;
        }
        __syncthreads();
        if (tid == 0) bar_red(IS_L1 ? bar1 : bar0);
    }
}

__global__ __launch_bounds__(512)
void lstm_pipeline(const float* __restrict__ xg0,
                   const float* __restrict__ w_hh0,
                   const float* __restrict__ w_ih1,
                   const float* __restrict__ w_hh1,
                   const float* __restrict__ b_ih1,
                   const float* __restrict__ b_hh1)
{
    extern __shared__ char smbase[];
    if (blockIdx.x < 64) {
        lstm_role<false>(xg0, w_hh0, nullptr, nullptr, nullptr,
                         blockIdx.x, smbase);
    } else {
        lstm_role<true>(nullptr, w_ih1, w_hh1, b_ih1, b_hh1,
                        blockIdx.x - 64, smbase);
    }
}

// L1 smem: 128*520*2 + 32*1032*2 + 8*68*4 + 2*32*65*4 = 217984 B
#define PIPE_SMEM (128 * SHH * 2 + 32 * 1032 * 2 + 8 * 68 * 4 + 2 * 32 * 65 * 4)

// ---------------------------------------------------------------------------
// kernel_launch
// ---------------------------------------------------------------------------
extern "C" void kernel_launch(void* const* d_in, const int* in_sizes, int n_in,
                              void* d_out, int out_size)
{
    const int*   X     = (const int*)  d_in[0];
    const float* emb   = (const float*)d_in[1];
    const float* w_ih0 = (const float*)d_in[2];
    const float* w_hh0 = (const float*)d_in[3];
    const float* b_ih0 = (const float*)d_in[4];
    const float* b_hh0 = (const float*)d_in[5];
    const float* w_ih1 = (const float*)d_in[6];
    const float* w_hh1 = (const float*)d_in[7];
    const float* b_ih1 = (const float*)d_in[8];
    const float* b_hh1 = (const float*)d_in[9];
    const float* Wout  = (const float*)d_in[10];
    const float* bout  = (const float*)d_in[11];
    float* out = (float*)d_out;

    float *xg, *hlast;
    __half *h0s, *h1s;
    cudaGetSymbolAddress((void**)&xg,    d_xg);
    cudaGetSymbolAddress((void**)&h0s,   d_h0seq);
    cudaGetSymbolAddress((void**)&h1s,   d_h1seq);
    cudaGetSymbolAddress((void**)&hlast, d_hlast);

    cudaFuncSetAttribute(lstm_pipeline,
                         cudaFuncAttributeMaxDynamicSharedMemorySize,
                         PIPE_SMEM);

    // 1) zero h_0 slots + barriers
    zero_h<<<32, 256>>>(h0s, h1s, SEQH);
    zero_bar<<<1, 32>>>();

    // 2) xg for layer 0 (embedding gather fused, tf32 mma)
    {
        dim3 grid(G4 / 128, MTOT / 128);
        gemm_mma2<<<grid, 512>>>(emb, w_ih0, xg, b_ih0, b_hh0, X,
                                 MTOT, G4, HIDN);
    }

    // 3) pipelined 2-layer recurrence (warp-specialized L1)
    lstm_pipeline<<<128, 512, PIPE_SMEM>>>(xg, w_hh0, w_ih1, w_hh1,
                                           b_ih1, b_hh1);

    // 4) logits = h1_last @ W^T + b  (guarded tf32 mma)
    {
        dim3 grid((NCLS + 127) / 128, 1);
        gemm_mma2<<<grid, 512>>>(hlast, Wout, out, bout, nullptr, nullptr,
                                 BATCH, NCLS, HIDN);
    }
}